// round 1
// baseline (speedup 1.0000x reference)
#include <cuda_runtime.h>
#include <cstdint>

#define Bn 64
#define Nn 50000
#define Ln 8
#define En 100000
#define Un 20000
#define Gn 20000
#define Rn 64
#define Dn 16
#define Cn 2
#define ND (Bn*Dn)   /* 1024 floats per node */

// Scratch (device globals: allocation-free rule)
__device__ float g_h[(size_t)Nn * ND];     // ~204.8 MB, layout [node][b][d]
__device__ float g_agg[(size_t)Un * ND];   // ~81.9 MB,  layout [u][b][d]
__device__ int   g_csr[Ln * En];
__device__ int   g_off[Ln * (Un + 1)];
__device__ int   g_cnt[Ln * Un];
__device__ int   g_cur[Ln * Un];

__global__ void k_zero_h() {
    size_t i = (size_t)blockIdx.x * blockDim.x + threadIdx.x;
    size_t n4 = (size_t)Nn * ND / 4;
    if (i < n4) ((float4*)g_h)[i] = make_float4(0.f, 0.f, 0.f, 0.f);
}

__global__ void k_zero_int() {
    int i = blockIdx.x * blockDim.x + threadIdx.x;
    if (i < Ln * Un) { g_cnt[i] = 0; g_cur[i] = 0; }
}

// h[gene_map[g]] = X[b,g] * w_in + b_in  (block = gene, thread = (b, j0))
__global__ void k_gene(const float* __restrict__ X, const float* __restrict__ w_in,
                       const float* __restrict__ b_in, const int* __restrict__ gene_map) {
    int g = blockIdx.x;
    int t = threadIdx.x;
    int b = t >> 2, j0 = (t & 3) << 2;
    int node = gene_map[g];
    float x = X[(size_t)b * Gn + g];
    float4 w  = *(const float4*)(w_in + j0);
    float4 bi = *(const float4*)(b_in + j0);
    float4 v = make_float4(fmaf(x, w.x, bi.x), fmaf(x, w.y, bi.y),
                           fmaf(x, w.z, bi.z), fmaf(x, w.w, bi.w));
    *(float4*)(g_h + (size_t)node * ND + t * 4) = v;
}

__global__ void k_hist(const int* __restrict__ dst_pos) {
    int i = blockIdx.x * blockDim.x + threadIdx.x;
    if (i < Ln * En) {
        int l = i / En;
        atomicAdd(&g_cnt[l * Un + dst_pos[i]], 1);
    }
}

// Exclusive scan of counts -> offsets, one block per layer.
__global__ void k_scan() {
    int l = blockIdx.x;
    const int* c = g_cnt + l * Un;
    int* o = g_off + l * (Un + 1);
    __shared__ int sh[1024];
    __shared__ int sbase;
    if (threadIdx.x == 0) sbase = 0;
    __syncthreads();
    for (int start = 0; start < Un; start += 1024) {
        int idx = start + (int)threadIdx.x;
        int v = (idx < Un) ? c[idx] : 0;
        sh[threadIdx.x] = v;
        __syncthreads();
        for (int st = 1; st < 1024; st <<= 1) {
            int tv = (threadIdx.x >= (unsigned)st) ? sh[threadIdx.x - st] : 0;
            __syncthreads();
            sh[threadIdx.x] += tv;
            __syncthreads();
        }
        if (idx < Un) o[idx] = sbase + sh[threadIdx.x] - v;  // exclusive
        __syncthreads();
        if (threadIdx.x == 0) sbase += sh[1023];
        __syncthreads();
    }
    if (threadIdx.x == 0) o[Un] = sbase;
}

__global__ void k_fill(const int* __restrict__ dst_pos) {
    int i = blockIdx.x * blockDim.x + threadIdx.x;
    if (i < Ln * En) {
        int l = i / En;
        int e = i - l * En;
        int u = dst_pos[i];
        int slot = g_off[l * (Un + 1) + u] + atomicAdd(&g_cur[l * Un + u], 1);
        g_csr[l * En + slot] = e;
    }
}

// Sort each bucket by edge id (deterministic sum order), then map edge id -> src node id.
__global__ void k_sortconv(const int* __restrict__ src) {
    int gid = blockIdx.x * blockDim.x + threadIdx.x;
    if (gid >= Ln * Un) return;
    int l = gid / Un;
    int u = gid - l * Un;
    int* seg = g_csr + l * En;
    int lo = g_off[l * (Un + 1) + u];
    int hi = g_off[l * (Un + 1) + u + 1];
    for (int i = lo + 1; i < hi; i++) {
        int key = seg[i];
        int j = i - 1;
        while (j >= lo && seg[j] > key) { seg[j + 1] = seg[j]; j--; }
        seg[j + 1] = key;
    }
    const int* sl = src + l * En;
    for (int i = lo; i < hi; i++) seg[i] = sl[seg[i]];
}

// Block = dst position u. Thread = (b = t>>2, output dims j0..j0+3).
// agg[u,b,j] = tanh( sum_edges h[src][b][:] @ W[:,j]  + bias[dst_unique[u]][j] )
__global__ __launch_bounds__(256, 4) void k_agg(int l, const float* __restrict__ W,
                                                const float* __restrict__ bias,
                                                const int* __restrict__ dstu) {
    const float* Wl = W + l * Dn * Dn;
    int u = blockIdx.x;
    int t = threadIdx.x;
    int b = t >> 2, q = t & 3;
    int j0 = q << 2;

    // Prepack W columns as f32x2 pairs in smem: sW[k][q*2 + {0,1}] = (W[k][j0],W[k][j0+1]),(W[k][j0+2],W[k][j0+3])
    __shared__ unsigned long long sW[16][8];
    if (t < 64) {
        int k = t >> 2, qq = t & 3;
        ulonglong2 wp = *(const ulonglong2*)(Wl + k * Dn + (qq << 2));
        sW[k][qq * 2]     = wp.x;
        sW[k][qq * 2 + 1] = wp.y;
    }
    __syncthreads();

    unsigned long long acc01 = 0ull, acc23 = 0ull;  // two packed f32x2 accumulators
    const int* csr = g_csr + l * En;
    const int* off = g_off + l * (Un + 1);
    int lo = off[u], hi = off[u + 1];

    for (int idx = lo; idx < hi; idx++) {
        int s = csr[idx];
        const float4* hp = (const float4*)(g_h + (size_t)s * ND + (b << 4));
        float4 v0 = hp[0], v1 = hp[1], v2 = hp[2], v3 = hp[3];
        float hr[16] = { v0.x, v0.y, v0.z, v0.w,  v1.x, v1.y, v1.z, v1.w,
                         v2.x, v2.y, v2.z, v2.w,  v3.x, v3.y, v3.z, v3.w };
        #pragma unroll
        for (int k = 0; k < 16; k++) {
            unsigned long long hk2;
            asm("mov.b64 %0, {%1, %1};" : "=l"(hk2) : "f"(hr[k]));
            asm("fma.rn.f32x2 %0, %1, %2, %0;" : "+l"(acc01) : "l"(hk2), "l"(sW[k][q * 2]));
            asm("fma.rn.f32x2 %0, %1, %2, %0;" : "+l"(acc23) : "l"(hk2), "l"(sW[k][q * 2 + 1]));
        }
    }

    int node = dstu[u];
    float4 bi = *(const float4*)(bias + (size_t)node * Dn + j0);
    float a0, a1, a2, a3;
    asm("mov.b64 {%0, %1}, %2;" : "=f"(a0), "=f"(a1) : "l"(acc01));
    asm("mov.b64 {%0, %1}, %2;" : "=f"(a2), "=f"(a3) : "l"(acc23));
    float4 v = make_float4(tanhf(a0 + bi.x), tanhf(a1 + bi.y),
                           tanhf(a2 + bi.z), tanhf(a3 + bi.w));
    *(float4*)(g_agg + (size_t)u * ND + t * 4) = v;
}

// h[dst_unique[l][u]][:] = agg[u][:]
__global__ void k_scatter(int l, const int* __restrict__ dst_unique) {
    int u = blockIdx.x;
    int t = threadIdx.x;
    int node = dst_unique[l * Un + u];
    ((float4*)(g_h + (size_t)node * ND))[t] = ((const float4*)(g_agg + (size_t)u * ND))[t];
}

// out[b,c] = sum_{r,j} h[root[r]][b][j] * W_head[c][r*16+j] + b_head[c]
__global__ void k_head(const int* __restrict__ roots, const float* __restrict__ Wh,
                       const float* __restrict__ bh, float* __restrict__ out) {
    int b = blockIdx.x;
    int t = threadIdx.x;
    float a0 = 0.f, a1 = 0.f;
    for (int i = t; i < Rn * Dn; i += 256) {
        int r = i >> 4, j = i & 15;
        float f = g_h[(size_t)roots[r] * ND + (b << 4) + j];
        a0 = fmaf(f, Wh[i], a0);
        a1 = fmaf(f, Wh[Rn * Dn + i], a1);
    }
    __shared__ float s0[256], s1[256];
    s0[t] = a0; s1[t] = a1;
    __syncthreads();
    for (int st = 128; st > 0; st >>= 1) {
        if (t < st) { s0[t] += s0[t + st]; s1[t] += s1[t + st]; }
        __syncthreads();
    }
    if (t == 0) {
        out[b * Cn + 0] = s0[0] + bh[0];
        out[b * Cn + 1] = s1[0] + bh[1];
    }
}

extern "C" void kernel_launch(void* const* d_in, const int* in_sizes, int n_in,
                              void* d_out, int out_size) {
    (void)in_sizes; (void)n_in; (void)out_size;
    const float* X          = (const float*)d_in[0];
    const float* w_in       = (const float*)d_in[1];
    const float* b_in       = (const float*)d_in[2];
    const float* W          = (const float*)d_in[3];
    const float* bias       = (const float*)d_in[4];
    const float* W_head     = (const float*)d_in[5];
    const float* b_head     = (const float*)d_in[6];
    const int*   gene_map   = (const int*)d_in[7];
    const int*   src        = (const int*)d_in[8];
    const int*   dst_pos    = (const int*)d_in[9];
    const int*   dst_unique = (const int*)d_in[10];
    const int*   root_ids   = (const int*)d_in[11];
    float* out = (float*)d_out;

    {
        size_t n4 = (size_t)Nn * ND / 4;
        k_zero_h<<<(unsigned)((n4 + 255) / 256), 256>>>();
    }
    k_zero_int<<<(Ln * Un + 255) / 256, 256>>>();
    k_gene<<<Gn, 256>>>(X, w_in, b_in, gene_map);

    // Batched CSR build for all 8 layers (depends only on dst_pos / src)
    k_hist<<<(Ln * En + 255) / 256, 256>>>(dst_pos);
    k_scan<<<Ln, 1024>>>();
    k_fill<<<(Ln * En + 255) / 256, 256>>>(dst_pos);
    k_sortconv<<<(Ln * Un + 255) / 256, 256>>>(src);

    for (int l = 0; l < Ln; l++) {
        k_agg<<<Un, 256>>>(l, W, bias, dst_unique + l * Un);
        k_scatter<<<Un, 256>>>(l, dst_unique);
    }

    k_head<<<Bn, 256>>>(root_ids, W_head, b_head, out);
}

// round 2
// speedup vs baseline: 1.3737x; 1.3737x over previous
#include <cuda_runtime.h>
#include <cstdint>

#define Bn 64
#define Nn 50000
#define Ln 8
#define En 100000
#define Un 20000
#define Gn 20000
#define Rn 64
#define Dn 16
#define Cn 2
#define ND (Bn*Dn)   /* 1024 floats per node */

// Scratch (device globals: allocation-free rule)
__device__ float g_h[(size_t)Nn * ND];     // ~204.8 MB, layout [node][b][d]
__device__ float g_agg[(size_t)Un * ND];   // ~81.9 MB,  layout [u][b][d]
__device__ int   g_csr[Ln * En];
__device__ int   g_off[Ln * (Un + 1)];
__device__ int   g_cnt[Ln * Un];
__device__ int   g_cur[Ln * Un];

__global__ void k_zero_h() {
    size_t i = (size_t)blockIdx.x * blockDim.x + threadIdx.x;
    size_t n4 = (size_t)Nn * ND / 4;
    if (i < n4) ((float4*)g_h)[i] = make_float4(0.f, 0.f, 0.f, 0.f);
}

__global__ void k_zero_int() {
    int i = blockIdx.x * blockDim.x + threadIdx.x;
    if (i < Ln * Un) { g_cnt[i] = 0; g_cur[i] = 0; }
}

// h[gene_map[g]] = X[b,g] * w_in + b_in  (block = gene, thread = (b, j0))
__global__ void k_gene(const float* __restrict__ X, const float* __restrict__ w_in,
                       const float* __restrict__ b_in, const int* __restrict__ gene_map) {
    int g = blockIdx.x;
    int t = threadIdx.x;
    int b = t >> 2, j0 = (t & 3) << 2;
    int node = gene_map[g];
    float x = X[(size_t)b * Gn + g];
    float4 w  = *(const float4*)(w_in + j0);
    float4 bi = *(const float4*)(b_in + j0);
    float4 v = make_float4(fmaf(x, w.x, bi.x), fmaf(x, w.y, bi.y),
                           fmaf(x, w.z, bi.z), fmaf(x, w.w, bi.w));
    *(float4*)(g_h + (size_t)node * ND + t * 4) = v;
}

__global__ void k_hist(const int* __restrict__ dst_pos) {
    int i = blockIdx.x * blockDim.x + threadIdx.x;
    if (i < Ln * En) {
        int l = i / En;
        atomicAdd(&g_cnt[l * Un + dst_pos[i]], 1);
    }
}

// Exclusive scan of counts -> offsets, one block per layer.
__global__ void k_scan() {
    int l = blockIdx.x;
    const int* c = g_cnt + l * Un;
    int* o = g_off + l * (Un + 1);
    __shared__ int sh[1024];
    __shared__ int sbase;
    if (threadIdx.x == 0) sbase = 0;
    __syncthreads();
    for (int start = 0; start < Un; start += 1024) {
        int idx = start + (int)threadIdx.x;
        int v = (idx < Un) ? c[idx] : 0;
        sh[threadIdx.x] = v;
        __syncthreads();
        for (int st = 1; st < 1024; st <<= 1) {
            int tv = (threadIdx.x >= (unsigned)st) ? sh[threadIdx.x - st] : 0;
            __syncthreads();
            sh[threadIdx.x] += tv;
            __syncthreads();
        }
        if (idx < Un) o[idx] = sbase + sh[threadIdx.x] - v;  // exclusive
        __syncthreads();
        if (threadIdx.x == 0) sbase += sh[1023];
        __syncthreads();
    }
    if (threadIdx.x == 0) o[Un] = sbase;
}

__global__ void k_fill(const int* __restrict__ dst_pos) {
    int i = blockIdx.x * blockDim.x + threadIdx.x;
    if (i < Ln * En) {
        int l = i / En;
        int e = i - l * En;
        int u = dst_pos[i];
        int slot = g_off[l * (Un + 1) + u] + atomicAdd(&g_cur[l * Un + u], 1);
        g_csr[l * En + slot] = e;
    }
}

// Sort each bucket by edge id (deterministic sum order), then map edge id -> src node id.
__global__ void k_sortconv(const int* __restrict__ src) {
    int gid = blockIdx.x * blockDim.x + threadIdx.x;
    if (gid >= Ln * Un) return;
    int l = gid / Un;
    int u = gid - l * Un;
    int* seg = g_csr + l * En;
    int lo = g_off[l * (Un + 1) + u];
    int hi = g_off[l * (Un + 1) + u + 1];
    for (int i = lo + 1; i < hi; i++) {
        int key = seg[i];
        int j = i - 1;
        while (j >= lo && seg[j] > key) { seg[j + 1] = seg[j]; j--; }
        seg[j + 1] = key;
    }
    const int* sl = src + l * En;
    for (int i = lo; i < hi; i++) seg[i] = sl[seg[i]];
}

// Block = dst position u. Thread = (b = t>>2, output dims j0..j0+3).
// agg[u,b,j] = tanh( sum_edges h[src][b][:] @ W[:,j]  + bias[dst_unique[u]][j] )
// W held in 64 registers per thread (NO shared loads in the hot loop);
// 2-deep software pipeline on the edge gather.
__global__ __launch_bounds__(256, 2) void k_agg(int l, const float* __restrict__ W,
                                                const float* __restrict__ bias,
                                                const int* __restrict__ dstu) {
    const float* Wl = W + l * Dn * Dn;
    int u = blockIdx.x;
    int t = threadIdx.x;
    int b = t >> 2, q = t & 3;
    int j0 = q << 2;

    // W[k][j0..j0+3] as two packed f32x2 pairs per k, in registers.
    unsigned long long w01[16], w23[16];
    #pragma unroll
    for (int k = 0; k < 16; k++) {
        ulonglong2 wp = *(const ulonglong2*)(Wl + k * Dn + j0);
        w01[k] = wp.x;
        w23[k] = wp.y;
    }

    unsigned long long acc01 = 0ull, acc23 = 0ull;
    const int* csr = g_csr + l * En;
    const int* off = g_off + l * (Un + 1);
    int lo = off[u], hi = off[u + 1];

    float4 c0, c1, c2, c3;
    if (lo < hi) {
        const float4* hp = (const float4*)(g_h + (size_t)csr[lo] * ND + (b << 4));
        c0 = hp[0]; c1 = hp[1]; c2 = hp[2]; c3 = hp[3];
    }

    for (int idx = lo; idx < hi; idx++) {
        float4 v0 = c0, v1 = c1, v2 = c2, v3 = c3;
        if (idx + 1 < hi) {  // prefetch next edge's source row
            const float4* hp = (const float4*)(g_h + (size_t)csr[idx + 1] * ND + (b << 4));
            c0 = hp[0]; c1 = hp[1]; c2 = hp[2]; c3 = hp[3];
        }
        #define AGG_STEP(kk, hval) { unsigned long long hk2_; \
            asm("mov.b64 %0, {%1, %1};" : "=l"(hk2_) : "f"(hval)); \
            asm("fma.rn.f32x2 %0, %1, %2, %0;" : "+l"(acc01) : "l"(hk2_), "l"(w01[kk])); \
            asm("fma.rn.f32x2 %0, %1, %2, %0;" : "+l"(acc23) : "l"(hk2_), "l"(w23[kk])); }
        AGG_STEP(0,  v0.x) AGG_STEP(1,  v0.y) AGG_STEP(2,  v0.z) AGG_STEP(3,  v0.w)
        AGG_STEP(4,  v1.x) AGG_STEP(5,  v1.y) AGG_STEP(6,  v1.z) AGG_STEP(7,  v1.w)
        AGG_STEP(8,  v2.x) AGG_STEP(9,  v2.y) AGG_STEP(10, v2.z) AGG_STEP(11, v2.w)
        AGG_STEP(12, v3.x) AGG_STEP(13, v3.y) AGG_STEP(14, v3.z) AGG_STEP(15, v3.w)
        #undef AGG_STEP
    }

    int node = dstu[u];
    float4 bi = *(const float4*)(bias + (size_t)node * Dn + j0);
    float a0, a1, a2, a3;
    asm("mov.b64 {%0, %1}, %2;" : "=f"(a0), "=f"(a1) : "l"(acc01));
    asm("mov.b64 {%0, %1}, %2;" : "=f"(a2), "=f"(a3) : "l"(acc23));
    float4 v = make_float4(tanhf(a0 + bi.x), tanhf(a1 + bi.y),
                           tanhf(a2 + bi.z), tanhf(a3 + bi.w));
    *(float4*)(g_agg + (size_t)u * ND + t * 4) = v;
}

// h[dst_unique[l][u]][:] = agg[u][:]
__global__ void k_scatter(int l, const int* __restrict__ dst_unique) {
    int u = blockIdx.x;
    int t = threadIdx.x;
    int node = dst_unique[l * Un + u];
    ((float4*)(g_h + (size_t)node * ND))[t] = ((const float4*)(g_agg + (size_t)u * ND))[t];
}

// out[b,c] = sum_{r,j} h[root[r]][b][j] * W_head[c][r*16+j] + b_head[c]
__global__ void k_head(const int* __restrict__ roots, const float* __restrict__ Wh,
                       const float* __restrict__ bh, float* __restrict__ out) {
    int b = blockIdx.x;
    int t = threadIdx.x;
    float a0 = 0.f, a1 = 0.f;
    for (int i = t; i < Rn * Dn; i += 256) {
        int r = i >> 4, j = i & 15;
        float f = g_h[(size_t)roots[r] * ND + (b << 4) + j];
        a0 = fmaf(f, Wh[i], a0);
        a1 = fmaf(f, Wh[Rn * Dn + i], a1);
    }
    __shared__ float s0[256], s1[256];
    s0[t] = a0; s1[t] = a1;
    __syncthreads();
    for (int st = 128; st > 0; st >>= 1) {
        if (t < st) { s0[t] += s0[t + st]; s1[t] += s1[t + st]; }
        __syncthreads();
    }
    if (t == 0) {
        out[b * Cn + 0] = s0[0] + bh[0];
        out[b * Cn + 1] = s1[0] + bh[1];
    }
}

extern "C" void kernel_launch(void* const* d_in, const int* in_sizes, int n_in,
                              void* d_out, int out_size) {
    (void)in_sizes; (void)n_in; (void)out_size;
    const float* X          = (const float*)d_in[0];
    const float* w_in       = (const float*)d_in[1];
    const float* b_in       = (const float*)d_in[2];
    const float* W          = (const float*)d_in[3];
    const float* bias       = (const float*)d_in[4];
    const float* W_head     = (const float*)d_in[5];
    const float* b_head     = (const float*)d_in[6];
    const int*   gene_map   = (const int*)d_in[7];
    const int*   src        = (const int*)d_in[8];
    const int*   dst_pos    = (const int*)d_in[9];
    const int*   dst_unique = (const int*)d_in[10];
    const int*   root_ids   = (const int*)d_in[11];
    float* out = (float*)d_out;

    {
        size_t n4 = (size_t)Nn * ND / 4;
        k_zero_h<<<(unsigned)((n4 + 255) / 256), 256>>>();
    }
    k_zero_int<<<(Ln * Un + 255) / 256, 256>>>();
    k_gene<<<Gn, 256>>>(X, w_in, b_in, gene_map);

    // Batched CSR build for all 8 layers (depends only on dst_pos / src)
    k_hist<<<(Ln * En + 255) / 256, 256>>>(dst_pos);
    k_scan<<<Ln, 1024>>>();
    k_fill<<<(Ln * En + 255) / 256, 256>>>(dst_pos);
    k_sortconv<<<(Ln * Un + 255) / 256, 256>>>(src);

    for (int l = 0; l < Ln; l++) {
        k_agg<<<Un, 256>>>(l, W, bias, dst_unique + l * Un);
        k_scatter<<<Un, 256>>>(l, dst_unique);
    }

    k_head<<<Bn, 256>>>(root_ids, W_head, b_head, out);
}

// round 3
// speedup vs baseline: 2.1038x; 1.5315x over previous
#include <cuda_runtime.h>
#include <cstdint>

#define Bn 64
#define Nn 50000
#define Ln 8
#define En 100000
#define Un 20000
#define Gn 20000
#define Rn 64
#define Dn 16
#define Cn 2
#define ND (Bn*Dn)   /* 1024 floats per node */
#define NPB 8        /* nodes per block in k_xform */

// Scratch (device globals: allocation-free rule)
__device__ float g_h[(size_t)Nn * ND];     // ~204.8 MB, layout [node][b][d]
__device__ float g_m[(size_t)Nn * ND];     // ~204.8 MB, transformed features
__device__ int   g_csr[Ln * En];
__device__ int   g_off[Ln * (Un + 1)];
__device__ int   g_cnt[Ln * Un];
__device__ int   g_cur[Ln * Un];

__global__ void k_zero_h() {
    size_t i = (size_t)blockIdx.x * blockDim.x + threadIdx.x;
    size_t n4 = (size_t)Nn * ND / 4;
    if (i < n4) ((float4*)g_h)[i] = make_float4(0.f, 0.f, 0.f, 0.f);
}

__global__ void k_zero_int() {
    int i = blockIdx.x * blockDim.x + threadIdx.x;
    if (i < Ln * Un) { g_cnt[i] = 0; g_cur[i] = 0; }
}

// h[gene_map[g]] = X[b,g] * w_in + b_in  (block = gene, thread = (b, j0))
__global__ void k_gene(const float* __restrict__ X, const float* __restrict__ w_in,
                       const float* __restrict__ b_in, const int* __restrict__ gene_map) {
    int g = blockIdx.x;
    int t = threadIdx.x;
    int b = t >> 2, j0 = (t & 3) << 2;
    int node = gene_map[g];
    float x = X[(size_t)b * Gn + g];
    float4 w  = *(const float4*)(w_in + j0);
    float4 bi = *(const float4*)(b_in + j0);
    float4 v = make_float4(fmaf(x, w.x, bi.x), fmaf(x, w.y, bi.y),
                           fmaf(x, w.z, bi.z), fmaf(x, w.w, bi.w));
    *(float4*)(g_h + (size_t)node * ND + t * 4) = v;
}

__global__ void k_hist(const int* __restrict__ dst_pos) {
    int i = blockIdx.x * blockDim.x + threadIdx.x;
    if (i < Ln * En) {
        int l = i / En;
        atomicAdd(&g_cnt[l * Un + dst_pos[i]], 1);
    }
}

// Exclusive scan of counts -> offsets, one block per layer.
__global__ void k_scan() {
    int l = blockIdx.x;
    const int* c = g_cnt + l * Un;
    int* o = g_off + l * (Un + 1);
    __shared__ int sh[1024];
    __shared__ int sbase;
    if (threadIdx.x == 0) sbase = 0;
    __syncthreads();
    for (int start = 0; start < Un; start += 1024) {
        int idx = start + (int)threadIdx.x;
        int v = (idx < Un) ? c[idx] : 0;
        sh[threadIdx.x] = v;
        __syncthreads();
        for (int st = 1; st < 1024; st <<= 1) {
            int tv = (threadIdx.x >= (unsigned)st) ? sh[threadIdx.x - st] : 0;
            __syncthreads();
            sh[threadIdx.x] += tv;
            __syncthreads();
        }
        if (idx < Un) o[idx] = sbase + sh[threadIdx.x] - v;  // exclusive
        __syncthreads();
        if (threadIdx.x == 0) sbase += sh[1023];
        __syncthreads();
    }
    if (threadIdx.x == 0) o[Un] = sbase;
}

__global__ void k_fill(const int* __restrict__ dst_pos) {
    int i = blockIdx.x * blockDim.x + threadIdx.x;
    if (i < Ln * En) {
        int l = i / En;
        int e = i - l * En;
        int u = dst_pos[i];
        int slot = g_off[l * (Un + 1) + u] + atomicAdd(&g_cur[l * Un + u], 1);
        g_csr[l * En + slot] = e;
    }
}

// Sort each bucket by edge id (deterministic sum order), then map edge id -> src node id.
__global__ void k_sortconv(const int* __restrict__ src) {
    int gid = blockIdx.x * blockDim.x + threadIdx.x;
    if (gid >= Ln * Un) return;
    int l = gid / Un;
    int u = gid - l * Un;
    int* seg = g_csr + l * En;
    int lo = g_off[l * (Un + 1) + u];
    int hi = g_off[l * (Un + 1) + u + 1];
    for (int i = lo + 1; i < hi; i++) {
        int key = seg[i];
        int j = i - 1;
        while (j >= lo && seg[j] > key) { seg[j + 1] = seg[j]; j--; }
        seg[j + 1] = key;
    }
    const int* sl = src + l * En;
    for (int i = lo; i < hi; i++) seg[i] = sl[seg[i]];
}

// m[n] = h[n] @ W_l for all nodes. Block handles NPB consecutive nodes.
// Thread = (b = t>>2, output dims j0..j0+3). W in registers, 1-deep h prefetch.
__global__ __launch_bounds__(256, 2) void k_xform(int l, const float* __restrict__ W) {
    const float* Wl = W + l * Dn * Dn;
    int t = threadIdx.x;
    int b = t >> 2, q = t & 3;
    int j0 = q << 2;
    int node0 = blockIdx.x * NPB;

    // W[k][j0..j0+3] as two packed f32x2 pairs per k, in registers.
    unsigned long long w01[16], w23[16];
    #pragma unroll
    for (int k = 0; k < 16; k++) {
        ulonglong2 wp = *(const ulonglong2*)(Wl + k * Dn + j0);
        w01[k] = wp.x;
        w23[k] = wp.y;
    }

    const float4* hp = (const float4*)(g_h + (size_t)node0 * ND + (b << 4));
    float4 c0 = hp[0], c1 = hp[1], c2 = hp[2], c3 = hp[3];

    #pragma unroll
    for (int nn = 0; nn < NPB; nn++) {
        float4 v0 = c0, v1 = c1, v2 = c2, v3 = c3;
        if (nn + 1 < NPB) {  // prefetch next node's row
            const float4* np = (const float4*)(g_h + (size_t)(node0 + nn + 1) * ND + (b << 4));
            c0 = np[0]; c1 = np[1]; c2 = np[2]; c3 = np[3];
        }
        unsigned long long acc01 = 0ull, acc23 = 0ull;
        #define XF_STEP(kk, hval) { unsigned long long hk2_; \
            asm("mov.b64 %0, {%1, %1};" : "=l"(hk2_) : "f"(hval)); \
            asm("fma.rn.f32x2 %0, %1, %2, %0;" : "+l"(acc01) : "l"(hk2_), "l"(w01[kk])); \
            asm("fma.rn.f32x2 %0, %1, %2, %0;" : "+l"(acc23) : "l"(hk2_), "l"(w23[kk])); }
        XF_STEP(0,  v0.x) XF_STEP(1,  v0.y) XF_STEP(2,  v0.z) XF_STEP(3,  v0.w)
        XF_STEP(4,  v1.x) XF_STEP(5,  v1.y) XF_STEP(6,  v1.z) XF_STEP(7,  v1.w)
        XF_STEP(8,  v2.x) XF_STEP(9,  v2.y) XF_STEP(10, v2.z) XF_STEP(11, v2.w)
        XF_STEP(12, v3.x) XF_STEP(13, v3.y) XF_STEP(14, v3.z) XF_STEP(15, v3.w)
        #undef XF_STEP
        float r0, r1, r2, r3;
        asm("mov.b64 {%0, %1}, %2;" : "=f"(r0), "=f"(r1) : "l"(acc01));
        asm("mov.b64 {%0, %1}, %2;" : "=f"(r2), "=f"(r3) : "l"(acc23));
        *(float4*)(g_m + (size_t)(node0 + nn) * ND + t * 4) = make_float4(r0, r1, r2, r3);
    }
}

// h[dst_unique[u]] = tanh( sum_edges m[src] + bias[dst_unique[u]] )
// Thread = (b, j0..j0+3): 1 LDG.128 per edge, 2-deep prefetch, fused scatter.
__global__ __launch_bounds__(256) void k_gather(int l, const float* __restrict__ bias,
                                                const int* __restrict__ dstu) {
    int u = blockIdx.x;
    int t = threadIdx.x;
    int j0 = (t & 3) << 2;

    const int* e = g_csr + l * En;
    const int* off = g_off + l * (Un + 1);
    int lo = off[u], hi = off[u + 1];
    int n = hi - lo;
    e += lo;

    float4 acc = make_float4(0.f, 0.f, 0.f, 0.f);
    float4 p0, p1;
    if (n > 0) p0 = *(const float4*)(g_m + (size_t)e[0] * ND + t * 4);
    if (n > 1) p1 = *(const float4*)(g_m + (size_t)e[1] * ND + t * 4);

    for (int i = 0; i < n; i++) {
        float4 v = p0;
        p0 = p1;
        if (i + 2 < n) p1 = *(const float4*)(g_m + (size_t)e[i + 2] * ND + t * 4);
        acc.x += v.x; acc.y += v.y; acc.z += v.z; acc.w += v.w;
    }

    int node = dstu[u];
    float4 bi = *(const float4*)(bias + (size_t)node * Dn + j0);
    float4 r = make_float4(tanhf(acc.x + bi.x), tanhf(acc.y + bi.y),
                           tanhf(acc.z + bi.z), tanhf(acc.w + bi.w));
    *(float4*)(g_h + (size_t)node * ND + t * 4) = r;
}

// out[b,c] = sum_{r,j} h[root[r]][b][j] * W_head[c][r*16+j] + b_head[c]
__global__ void k_head(const int* __restrict__ roots, const float* __restrict__ Wh,
                       const float* __restrict__ bh, float* __restrict__ out) {
    int b = blockIdx.x;
    int t = threadIdx.x;
    float a0 = 0.f, a1 = 0.f;
    for (int i = t; i < Rn * Dn; i += 256) {
        int r = i >> 4, j = i & 15;
        float f = g_h[(size_t)roots[r] * ND + (b << 4) + j];
        a0 = fmaf(f, Wh[i], a0);
        a1 = fmaf(f, Wh[Rn * Dn + i], a1);
    }
    __shared__ float s0[256], s1[256];
    s0[t] = a0; s1[t] = a1;
    __syncthreads();
    for (int st = 128; st > 0; st >>= 1) {
        if (t < st) { s0[t] += s0[t + st]; s1[t] += s1[t + st]; }
        __syncthreads();
    }
    if (t == 0) {
        out[b * Cn + 0] = s0[0] + bh[0];
        out[b * Cn + 1] = s1[0] + bh[1];
    }
}

extern "C" void kernel_launch(void* const* d_in, const int* in_sizes, int n_in,
                              void* d_out, int out_size) {
    (void)in_sizes; (void)n_in; (void)out_size;
    const float* X          = (const float*)d_in[0];
    const float* w_in       = (const float*)d_in[1];
    const float* b_in       = (const float*)d_in[2];
    const float* W          = (const float*)d_in[3];
    const float* bias       = (const float*)d_in[4];
    const float* W_head     = (const float*)d_in[5];
    const float* b_head     = (const float*)d_in[6];
    const int*   gene_map   = (const int*)d_in[7];
    const int*   src        = (const int*)d_in[8];
    const int*   dst_pos    = (const int*)d_in[9];
    const int*   dst_unique = (const int*)d_in[10];
    const int*   root_ids   = (const int*)d_in[11];
    float* out = (float*)d_out;

    {
        size_t n4 = (size_t)Nn * ND / 4;
        k_zero_h<<<(unsigned)((n4 + 255) / 256), 256>>>();
    }
    k_zero_int<<<(Ln * Un + 255) / 256, 256>>>();
    k_gene<<<Gn, 256>>>(X, w_in, b_in, gene_map);

    // Batched CSR build for all 8 layers (depends only on dst_pos / src)
    k_hist<<<(Ln * En + 255) / 256, 256>>>(dst_pos);
    k_scan<<<Ln, 1024>>>();
    k_fill<<<(Ln * En + 255) / 256, 256>>>(dst_pos);
    k_sortconv<<<(Ln * Un + 255) / 256, 256>>>(src);

    for (int l = 0; l < Ln; l++) {
        k_xform<<<Nn / NPB, 256>>>(l, W);
        k_gather<<<Un, 256>>>(l, bias, dst_unique + l * Un);
    }

    k_head<<<Bn, 256>>>(root_ids, W_head, b_head, out);
}